// round 4
// baseline (speedup 1.0000x reference)
#include <cuda_runtime.h>
#include <cuda_bf16.h>

#define TB 256
#define BM 128
#define BN 64
#define BK 16

// Scratch for the two linear projections: [8, 2048, 256] f32 each.
__device__ __align__(16) float g_c1[8 * 2048 * 256];
__device__ __align__(16) float g_c2[8 * 2048 * 256];

// Elementwise epilogue:
//   sig = sigmoid(s); c = 100*sig + 1e-5; cc = 1/(2 c^2); out = exp(-a^2 * cc)
// Fused to 3 MUFU ops (EX2, RCP, EX2):
//   t = e^{-s}; u = 1+t; c = (100 + 1e-5 u)/u
//   1/(sqrt2*c) = u * rcp(100 + 1e-5 u) * (1/sqrt2);  cc = (that)^2
__device__ __forceinline__ float epi(float s, float a) {
    float t = __expf(fminf(-s, 80.0f));               // MUFU ex2 (clamped: no inf)
    float u = 1.0f + t;
    float q = __fdividef(u, fmaf(1e-5f, u, 100.0f));  // MUFU rcp
    q *= 0.70710678f;
    float cc = q * q;                                  // = 1/(2 c^2)
    return __expf(-(a * a * cc));                      // MUFU ex2
}

// ---------------------------------------------------------------------------
// Projection: C = A(M x K) * W(N x K)^T, K = 256.
// A = v (16384 x 256), W = W1 or W2 (256 x 256), C = g_c1 or g_c2.
// Tile: 128 x 64, 256 threads, 8x4 outputs/thread.
// ---------------------------------------------------------------------------
__global__ __launch_bounds__(TB) void proj_kernel(
    const float* __restrict__ v,
    const float* __restrict__ W1,
    const float* __restrict__ W2)
{
    const int K = 256;
    const float* A = v;
    const float* B = blockIdx.z ? W2 : W1;
    float* C = blockIdx.z ? g_c2 : g_c1;

    __shared__ __align__(16) float As[BK][BM + 4];
    __shared__ __align__(16) float Bs[BK][BN + 4];

    int m0 = blockIdx.x * BM;
    int n0 = blockIdx.y * BN;
    int tid = threadIdx.x;
    int tr = tid >> 4, tc = tid & 15;       // 16x16 compute layout
    int lrA = tid >> 1, lcA = (tid & 1) * 8;
    int lrB = tid >> 2, lcB = (tid & 3) * 4;

    float acc[8][4];
#pragma unroll
    for (int i = 0; i < 8; i++)
#pragma unroll
        for (int j = 0; j < 4; j++) acc[i][j] = 0.0f;

    for (int k0 = 0; k0 < K; k0 += BK) {
        float4 a0 = *(const float4*)(A + (size_t)(m0 + lrA) * K + k0 + lcA);
        float4 a1 = *(const float4*)(A + (size_t)(m0 + lrA) * K + k0 + lcA + 4);
        float4 b0 = *(const float4*)(B + (size_t)(n0 + lrB) * K + k0 + lcB);

        As[lcA + 0][lrA] = a0.x; As[lcA + 1][lrA] = a0.y;
        As[lcA + 2][lrA] = a0.z; As[lcA + 3][lrA] = a0.w;
        As[lcA + 4][lrA] = a1.x; As[lcA + 5][lrA] = a1.y;
        As[lcA + 6][lrA] = a1.z; As[lcA + 7][lrA] = a1.w;
        Bs[lcB + 0][lrB] = b0.x; Bs[lcB + 1][lrB] = b0.y;
        Bs[lcB + 2][lrB] = b0.z; Bs[lcB + 3][lrB] = b0.w;
        __syncthreads();

#pragma unroll
        for (int kk = 0; kk < BK; kk++) {
            float4 av0 = *(const float4*)&As[kk][tr * 8];
            float4 av1 = *(const float4*)&As[kk][tr * 8 + 4];
            float4 bv  = *(const float4*)&Bs[kk][tc * 4];
            float am[8] = {av0.x, av0.y, av0.z, av0.w, av1.x, av1.y, av1.z, av1.w};
            float bm[4] = {bv.x, bv.y, bv.z, bv.w};
#pragma unroll
            for (int i = 0; i < 8; i++)
#pragma unroll
                for (int j = 0; j < 4; j++)
                    acc[i][j] = fmaf(am[i], bm[j], acc[i][j]);
        }
        __syncthreads();
    }

#pragma unroll
    for (int i = 0; i < 8; i++) {
        float4 o4 = make_float4(acc[i][0], acc[i][1], acc[i][2], acc[i][3]);
        *(float4*)(C + (size_t)(m0 + tr * 8 + i) * 256 + n0 + tc * 4) = o4;
    }
}

// ---------------------------------------------------------------------------
// Score GEMM + fused epilogue:
//   s[b,n,m] = sum_o c1[b,n,o] * c2[b,m,o]  (2048 x 2048 x 256 per batch)
//   out[b,n,m] = epi(s, adj[b,n,m])
// Tile: 128 (n) x 64 (m), 256 threads, 8x4 outputs/thread.
// ---------------------------------------------------------------------------
__global__ __launch_bounds__(TB) void score_kernel(
    const float* __restrict__ adj,
    float* __restrict__ out)
{
    const int K = 256;
    const int NN = 2048;
    int b = blockIdx.z;
    const float* A = g_c1 + (size_t)b * NN * K;   // rows: n
    const float* B = g_c2 + (size_t)b * NN * K;   // rows: m
    const float* adj_b = adj + (size_t)b * NN * NN;
    float* out_b = out + (size_t)b * NN * NN;

    __shared__ __align__(16) float As[BK][BM + 4];
    __shared__ __align__(16) float Bs[BK][BN + 4];

    int n0 = blockIdx.x * BM;   // row tile (n)
    int m0 = blockIdx.y * BN;   // col tile (m)
    int tid = threadIdx.x;
    int tr = tid >> 4, tc = tid & 15;
    int lrA = tid >> 1, lcA = (tid & 1) * 8;
    int lrB = tid >> 2, lcB = (tid & 3) * 4;

    float acc[8][4];
#pragma unroll
    for (int i = 0; i < 8; i++)
#pragma unroll
        for (int j = 0; j < 4; j++) acc[i][j] = 0.0f;

    for (int k0 = 0; k0 < K; k0 += BK) {
        float4 a0 = *(const float4*)(A + (size_t)(n0 + lrA) * K + k0 + lcA);
        float4 a1 = *(const float4*)(A + (size_t)(n0 + lrA) * K + k0 + lcA + 4);
        float4 b0 = *(const float4*)(B + (size_t)(m0 + lrB) * K + k0 + lcB);

        As[lcA + 0][lrA] = a0.x; As[lcA + 1][lrA] = a0.y;
        As[lcA + 2][lrA] = a0.z; As[lcA + 3][lrA] = a0.w;
        As[lcA + 4][lrA] = a1.x; As[lcA + 5][lrA] = a1.y;
        As[lcA + 6][lrA] = a1.z; As[lcA + 7][lrA] = a1.w;
        Bs[lcB + 0][lrB] = b0.x; Bs[lcB + 1][lrB] = b0.y;
        Bs[lcB + 2][lrB] = b0.z; Bs[lcB + 3][lrB] = b0.w;
        __syncthreads();

#pragma unroll
        for (int kk = 0; kk < BK; kk++) {
            float4 av0 = *(const float4*)&As[kk][tr * 8];
            float4 av1 = *(const float4*)&As[kk][tr * 8 + 4];
            float4 bv  = *(const float4*)&Bs[kk][tc * 4];
            float am[8] = {av0.x, av0.y, av0.z, av0.w, av1.x, av1.y, av1.z, av1.w};
            float bm[4] = {bv.x, bv.y, bv.z, bv.w};
#pragma unroll
            for (int i = 0; i < 8; i++)
#pragma unroll
                for (int j = 0; j < 4; j++)
                    acc[i][j] = fmaf(am[i], bm[j], acc[i][j]);
        }
        __syncthreads();
    }

    // Fused epilogue: read adj, apply transform, write norm_adj.
#pragma unroll
    for (int i = 0; i < 8; i++) {
        int row = n0 + tr * 8 + i;
        size_t base = (size_t)row * NN + m0 + tc * 4;
        float4 a4 = *(const float4*)(adj_b + base);
        float4 o4;
        o4.x = epi(acc[i][0], a4.x);
        o4.y = epi(acc[i][1], a4.y);
        o4.z = epi(acc[i][2], a4.z);
        o4.w = epi(acc[i][3], a4.w);
        *(float4*)(out_b + base) = o4;
    }
}

extern "C" void kernel_launch(void* const* d_in, const int* in_sizes, int n_in,
                              void* d_out, int out_size) {
    const float* v   = (const float*)d_in[0];
    const float* adj = (const float*)d_in[1];
    const float* W1  = (const float*)d_in[2];
    const float* W2  = (const float*)d_in[3];
    float* out = (float*)d_out;

    const long adj_elems = 8L * 2048 * 2048;      // 33,554,432
    long off = (long)out_size - adj_elems;        // leading v-passthrough elems
    if (off < 0) off = 0;

    if (off > 0) {
        // Output tuple element 0 is v unchanged.
        cudaMemcpyAsync(out, v, (size_t)off * sizeof(float),
                        cudaMemcpyDeviceToDevice, 0);
    }
    float* norm_adj = out + off;

    // Projections: c1 = v @ W1^T, c2 = v @ W2^T
    dim3 pgrid(16384 / BM, 256 / BN, 2);
    proj_kernel<<<pgrid, TB>>>(v, W1, W2);

    // Score GEMM + fused normalization epilogue
    dim3 sgrid(2048 / BM, 2048 / BN, 8);
    score_kernel<<<sgrid, TB>>>(adj, norm_adj);
}